// round 16
// baseline (speedup 1.0000x reference)
#include <cuda_runtime.h>
#include <cstdint>

#define NODES 32
#define NGRAPH 4096
#define FEAT 10
#define EPG 256
#define EDGES_TOTAL (NGRAPH * EPG)

#define XSTR 68     // X row stride [i][k]; bank 4g+t4 on A-loads (bijective)
#define WSTR 68     // Wt row stride [k][m] (transposed weights); bank 4g+t4 on B-loads
#define HTS  36     // Ht row stride [col][j] (transposed H); bank 4g+t4 on B-loads
#define AJ   136    // alphaT row stride [j][hd*32+i]; bank 8t4+g on A-loads
#define QSTR 36     // attention Q/K/V row stride
#define CSTR 33     // multiplicity row stride

typedef unsigned long long ull;

struct Smem {
    float WA[4352];   // Wt[k][68] (64 rows) <-> alphaT[j][136]; attn Wq/Wk/Wv^T
    float Ht[2304];   // GAT H^T [col][36] (64 rows); attn Q/K/V stride 36; pool scratch
    float X[2176];    // activations [i][68]
    float C[1056];    // multiplicity [i][33]; attn att_in [s][32]
    float ES[128], ED[128];
    float AS[64], AD[64], B[64];
};

// ---------- f32x2 helpers (attention phase) ----------
__device__ __forceinline__ void fma2(ull& acc, ull a, ull b) {
    asm("fma.rn.f32x2 %0, %1, %2, %0;" : "+l"(acc) : "l"(a), "l"(b));
}
__device__ __forceinline__ float red2(ull v) {
    float lo, hi;
    asm("mov.b64 {%0,%1}, %2;" : "=f"(lo), "=f"(hi) : "l"(v));
    return lo + hi;
}
__device__ __forceinline__ ulonglong2 ld2(const float* p) { return *(const ulonglong2*)p; }
__device__ __forceinline__ float lrelu(float v, float s) { return v > 0.f ? v : v * s; }

// ---------- tf32 split: hi = rna(f) (exactly representable), lo = f - hi (exact FSUB) ----------
struct TF2 { uint32_t hi, lo; };
__device__ __forceinline__ TF2 tf32x(float f) {
    TF2 r;
    asm("cvt.rna.tf32.f32 %0, %1;" : "=r"(r.hi) : "f"(f));
    r.lo = __float_as_uint(f - __uint_as_float(r.hi));
    return r;
}
__device__ __forceinline__ void mma8(float* d, const uint32_t* a, const uint32_t* b) {
    asm("mma.sync.aligned.m16n8k8.row.col.f32.tf32.tf32.f32 "
        "{%0,%1,%2,%3}, {%4,%5,%6,%7}, {%8,%9}, {%0,%1,%2,%3};"
        : "+f"(d[0]), "+f"(d[1]), "+f"(d[2]), "+f"(d[3])
        : "r"(a[0]), "r"(a[1]), "r"(a[2]), "r"(a[3]), "r"(b[0]), "r"(b[1]));
}
__device__ __forceinline__ void mma3x(float* d, const TF2* a, const TF2* b) {
    uint32_t ah[4] = {a[0].hi, a[1].hi, a[2].hi, a[3].hi};
    uint32_t al[4] = {a[0].lo, a[1].lo, a[2].lo, a[3].lo};
    uint32_t bh[2] = {b[0].hi, b[1].hi};
    uint32_t bl[2] = {b[0].lo, b[1].lo};
    mma8(d, al, bh);
    mma8(d, ah, bl);
    mma8(d, ah, bh);
}

template<int CIN, int CINP, int H4>
__device__ void gat_layer(Smem& s,
                          const float* __restrict__ W, const float* __restrict__ as_,
                          const float* __restrict__ ad_, const float* __restrict__ b_,
                          int tid)
{
    const int lane = tid & 31;
    const int w    = tid >> 5;     // warp 0..3, owns cols 16w..16w+15 (= head w for H4=4)
    const int g    = lane >> 2;    // 0..7  (m/n index of mma fragments)
    const int t4   = lane & 3;     // 0..3  (k index of mma fragments)

    __syncthreads();   // prior X writes / prior alphaT (in WA) reads complete

    // ---- stage Wt[k][m] = W[m][k] transposed; conflict-free scalar pattern ----
    {
        const int kk = (tid & 7) + 8 * (tid >> 5);     // 0..31
        const int m0 = (tid >> 3) & 3;
#pragma unroll
        for (int kh = 0; kh < 64; kh += 32) {
#pragma unroll
            for (int p = 0; p < CINP / 4; p++) {
                int m = m0 + 4 * p;
                s.WA[(kk + kh) * WSTR + m] = (m < CIN) ? W[m * 64 + kk + kh] : 0.f;
            }
        }
    }
    if (tid < 64) { s.AS[tid] = as_[tid]; s.AD[tid] = ad_[tid]; s.B[tid] = b_[tid]; }
    __syncthreads();

    // ---- mm1: H = X @ W  (warp w -> 16 cols), 3xTF32 ----
    float d[2][2][4] = {};
#pragma unroll
    for (int st = 0; st < CINP / 8; st++) {
        const int m0 = 8 * st;
        TF2 a[2][4], b[2][2];
#pragma unroll
        for (int ti = 0; ti < 2; ti++) {
            int r0 = 16 * ti + g;
            a[ti][0] = tf32x(s.X[r0 * XSTR + m0 + t4]);
            a[ti][1] = tf32x(s.X[(r0 + 8) * XSTR + m0 + t4]);
            a[ti][2] = tf32x(s.X[r0 * XSTR + m0 + t4 + 4]);
            a[ti][3] = tf32x(s.X[(r0 + 8) * XSTR + m0 + t4 + 4]);
        }
#pragma unroll
        for (int nt = 0; nt < 2; nt++) {
            int col = 16 * w + 8 * nt + g;
            b[nt][0] = tf32x(s.WA[col * WSTR + m0 + t4]);      // bank 4g+t4: bijective
            b[nt][1] = tf32x(s.WA[col * WSTR + m0 + t4 + 4]);
        }
#pragma unroll
        for (int ti = 0; ti < 2; ti++)
#pragma unroll
            for (int nt = 0; nt < 2; nt++)
                mma3x(d[ti][nt], a[ti], b[nt]);
    }

    // ---- e_s/e_d partials straight from D-fragments ----
    {
        float esp[4] = {0.f, 0.f, 0.f, 0.f}, edp[4] = {0.f, 0.f, 0.f, 0.f};
#pragma unroll
        for (int ti = 0; ti < 2; ti++)
#pragma unroll
            for (int nt = 0; nt < 2; nt++) {
                int cb = 16 * w + 8 * nt + 2 * t4;
                float s0 = s.AS[cb], s1 = s.AS[cb + 1];
                float a0 = s.AD[cb], a1 = s.AD[cb + 1];
                esp[2 * ti]     += d[ti][nt][0] * s0 + d[ti][nt][1] * s1;
                esp[2 * ti + 1] += d[ti][nt][2] * s0 + d[ti][nt][3] * s1;
                edp[2 * ti]     += d[ti][nt][0] * a0 + d[ti][nt][1] * a1;
                edp[2 * ti + 1] += d[ti][nt][2] * a0 + d[ti][nt][3] * a1;
            }
#pragma unroll
        for (int m = 1; m <= 2; m <<= 1)
#pragma unroll
            for (int r = 0; r < 4; r++) {
                esp[r] += __shfl_xor_sync(0xFFFFFFFF, esp[r], m);
                edp[r] += __shfl_xor_sync(0xFFFFFFFF, edp[r], m);
            }
        if (t4 == 0) {
#pragma unroll
            for (int r = 0; r < 4; r++) {
                int row = 16 * (r >> 1) + 8 * (r & 1) + g;
                s.ES[w * 32 + row] = esp[r];
                s.ED[w * 32 + row] = edp[r];
            }
        }
    }

    // ---- store H fragments transposed Ht[col][j] (bank 8t4+g: conflict-free) ----
#pragma unroll
    for (int ti = 0; ti < 2; ti++)
#pragma unroll
        for (int nt = 0; nt < 2; nt++) {
            int r0 = 16 * ti + g, c0 = 16 * w + 8 * nt + 2 * t4;
            s.Ht[c0 * HTS + r0]           = d[ti][nt][0];
            s.Ht[(c0 + 1) * HTS + r0]     = d[ti][nt][1];
            s.Ht[c0 * HTS + r0 + 8]       = d[ti][nt][2];
            s.Ht[(c0 + 1) * HTS + r0 + 8] = d[ti][nt][3];
        }

    if (H4 == 1) {
        __syncthreads();
        if (tid < 32) {
            s.ES[tid] = s.ES[tid] + s.ES[32 + tid] + s.ES[64 + tid] + s.ES[96 + tid];
            s.ED[tid] = s.ED[tid] + s.ED[32 + tid] + s.ED[64 + tid] + s.ED[96 + tid];
        }
        __syncthreads();
    } else {
        __syncwarp();
    }

    // ---- multiplicity-weighted softmax (unmasked max: alpha invariant to shift);
    //      alphaT[j][hd*32+i] -> WA (weights dead) ----
    if (tid < 32 * H4) {
        const int i = tid & 31, hd = tid >> 5;
        const float edi = s.ED[hd * 32 + i];
        const float* esr = &s.ES[hd * 32];
        const float* crow = &s.C[i * CSTR];
        float ev[32];
        float mx = -1e30f;
#pragma unroll
        for (int j = 0; j < 32; j++) {
            float e = lrelu(esr[j] + edi, 0.2f);
            ev[j] = e;
            mx = fmaxf(mx, e);
        }
        float den = 0.f;
#pragma unroll
        for (int j = 0; j < 32; j++) {
            float wv = crow[j] * __expf(ev[j] - mx);
            ev[j] = wv; den += wv;
        }
        float inv = 1.f / (den + 1e-16f);
        float* at0 = &s.WA[hd * 32 + i];
#pragma unroll
        for (int j = 0; j < 32; j++)
            at0[j * AJ] = ev[j] * inv;     // bank 8j+i per instr: conflict-free
    }
    if (H4 == 1) __syncthreads(); else __syncwarp();

    // ---- mm2: X[i][col] = lrelu( alpha_hd @ H + b ), 3xTF32 ----
    {
        const int hd = (H4 == 4) ? w : 0;
        const float* AT = &s.WA[hd * 32];
        float d2[2][2][4] = {};
#pragma unroll
        for (int st = 0; st < 4; st++) {
            const int j0 = 8 * st;
            TF2 a[2][4], b[2][2];
#pragma unroll
            for (int ti = 0; ti < 2; ti++) {
                int r0 = 16 * ti + g;
                a[ti][0] = tf32x(AT[(j0 + t4) * AJ + r0]);          // bank 8t4+g
                a[ti][1] = tf32x(AT[(j0 + t4) * AJ + r0 + 8]);
                a[ti][2] = tf32x(AT[(j0 + t4 + 4) * AJ + r0]);
                a[ti][3] = tf32x(AT[(j0 + t4 + 4) * AJ + r0 + 8]);
            }
#pragma unroll
            for (int nt = 0; nt < 2; nt++) {
                int col = 16 * w + 8 * nt + g;
                b[nt][0] = tf32x(s.Ht[col * HTS + j0 + t4]);        // bank 4g+t4
                b[nt][1] = tf32x(s.Ht[col * HTS + j0 + t4 + 4]);
            }
#pragma unroll
            for (int ti = 0; ti < 2; ti++)
#pragma unroll
                for (int nt = 0; nt < 2; nt++)
                    mma3x(d2[ti][nt], a[ti], b[nt]);
        }
#pragma unroll
        for (int ti = 0; ti < 2; ti++)
#pragma unroll
            for (int nt = 0; nt < 2; nt++) {
                int r0 = 16 * ti + g, col = 16 * w + 8 * nt + 2 * t4;
                float b0 = s.B[col], b1 = s.B[col + 1];
                *(float2*)&s.X[r0 * XSTR + col] =
                    make_float2(lrelu(d2[ti][nt][0] + b0, 0.01f), lrelu(d2[ti][nt][1] + b1, 0.01f));
                *(float2*)&s.X[(r0 + 8) * XSTR + col] =
                    make_float2(lrelu(d2[ti][nt][2] + b0, 0.01f), lrelu(d2[ti][nt][3] + b1, 0.01f));
            }
    }
}

__global__ __launch_bounds__(128, 5) void gnn_kernel(
    const float* __restrict__ x, const int* __restrict__ ei,
    const float* __restrict__ Wq, const float* __restrict__ Wk, const float* __restrict__ Wv,
    const float* __restrict__ W1, const float* __restrict__ a1s, const float* __restrict__ a1d, const float* __restrict__ b1,
    const float* __restrict__ W2, const float* __restrict__ a2s, const float* __restrict__ a2d, const float* __restrict__ b2,
    const float* __restrict__ W3, const float* __restrict__ a3s, const float* __restrict__ a3d, const float* __restrict__ b3,
    const float* __restrict__ W4, const float* __restrict__ a4s, const float* __restrict__ a4d, const float* __restrict__ b4,
    const float* __restrict__ fcW, const float* __restrict__ fcb,
    float* __restrict__ out, int out_half)
{
    __shared__ Smem s;
    const int tid = threadIdx.x;
    const int g = blockIdx.x;

    const bool is64 = (ei[2 * (size_t)EDGES_TOTAL - 1] == 0);

    // ---------------- Attention layer (f32 FFMA2 path) ----------------
    // P1: Wq/Wk/Wv transposed into WA [c][i] stride QSTR; lanes i-low(4) x c-low(8)
    {
        const int il = tid & 3;
        const int cl = (tid >> 2) & 7;
        const int ih = tid >> 5;
#pragma unroll
        for (int e = 0; e < 24; e++) {
            int which = e >> 3, f = e & 7;
            int i = il + 4 * ih + 16 * (f & 1);
            int c = cl + 8 * ((f >> 1) & 1) + 16 * (f >> 2);
            const float* Wsrc = (which == 0) ? Wq : (which == 1) ? Wk : Wv;
            s.WA[which * 1280 + c * QSTR + i] = Wsrc[i * 32 + c];
        }
    }
    for (int t = tid; t < 320; t += 128) {
        int si = t >> 5, ii = t & 31;
        s.C[si * 32 + ii] = x[(size_t)(g * 32 + ii) * FEAT + si];
    }
    __syncthreads();

    // P2: Q,K,V [s][c] stride 36 -> Ht at 0/360/720
    for (int o = tid; o < 960; o += 128) {
        int which = o / 320, r = o - which * 320;
        int si = r >> 5, c = r & 31;
        const float* wt = &s.WA[which * 1280 + c * QSTR];
        const float* at = &s.C[si * 32];
        ull acc = 0;
#pragma unroll
        for (int ig = 0; ig < 32; ig += 4) {
            ulonglong2 a2 = ld2(at + ig), w2 = ld2(wt + ig);
            fma2(acc, a2.x, w2.x); fma2(acc, a2.y, w2.y);
        }
        s.Ht[which * 360 + si * 36 + c] = red2(acc);
    }
    __syncthreads();

    // P3: scores [s][t] -> ES; zero C
    for (int t = tid; t < NODES * CSTR; t += 128) s.C[t] = 0.f;
    if (tid < 100) {
        int si = tid / 10, ti = tid - si * 10;
        ull acc = 0;
#pragma unroll
        for (int cg = 0; cg < 32; cg += 4) {
            ulonglong2 q2 = ld2(&s.Ht[si * 36 + cg]);
            ulonglong2 k2 = ld2(&s.Ht[360 + ti * 36 + cg]);
            fma2(acc, q2.x, k2.x); fma2(acc, q2.y, k2.y);
        }
        s.ES[si * 10 + ti] = red2(acc);
    }
    __syncthreads();

    // P4: multiplicity matrix + attention row softmax
#pragma unroll
    for (int half = 0; half < 2; half++) {
        size_t eg = (size_t)g * EPG + tid + 128 * half;
        int srcv, dstv;
        if (is64) {
            srcv = ei[2 * eg];
            dstv = ei[2 * ((size_t)EDGES_TOTAL + eg)];
        } else {
            srcv = ei[eg];
            dstv = ei[(size_t)EDGES_TOTAL + eg];
        }
        int sl = srcv - g * 32, dl = dstv - g * 32;
        atomicAdd(&s.C[dl * CSTR + sl], 1.0f);
    }
    if (tid < 32) atomicAdd(&s.C[tid * CSTR + tid], 1.0f);  // self-loops
    if (tid < 10) {
        float mx = -1e30f;
#pragma unroll
        for (int t2 = 0; t2 < 10; t2++) mx = fmaxf(mx, s.ES[tid * 10 + t2]);
        float e[10], sum = 0.f;
#pragma unroll
        for (int t2 = 0; t2 < 10; t2++) { e[t2] = __expf(s.ES[tid * 10 + t2] - mx); sum += e[t2]; }
        float inv = 1.f / sum;
#pragma unroll
        for (int t2 = 0; t2 < 10; t2++) s.ES[tid * 10 + t2] = e[t2] * inv;
    }
    __syncthreads();

    // P5: att out[s][i] -> X[i][s]; zero pad cols 10..15
    for (int t = tid; t < 320; t += 128) {
        int si = t >> 5, ii = t & 31;
        float acc = 0.f;
#pragma unroll
        for (int t2 = 0; t2 < 10; t2++)
            acc += s.ES[si * 10 + t2] * s.Ht[720 + t2 * 36 + ii];
        s.X[ii * XSTR + si] = acc;
    }
    for (int t = tid; t < 192; t += 128) {
        int ii = t & 31, cc = 10 + (t >> 5);
        s.X[ii * XSTR + cc] = 0.f;
    }

    // ---------------- GAT stack (tensor-core 3xTF32) ----------------
    gat_layer<10, 16, 4>(s, W1, a1s, a1d, b1, tid);
    gat_layer<64, 64, 4>(s, W2, a2s, a2d, b2, tid);
    gat_layer<64, 64, 4>(s, W3, a3s, a3d, b3, tid);
    gat_layer<64, 64, 1>(s, W4, a4s, a4d, b4, tid);
    __syncthreads();

    // ---------------- Mean pool + FC + softmax ----------------
    if (tid < 64) {
        float acc = 0.f;
#pragma unroll
        for (int i = 0; i < 32; i++) acc += s.X[i * XSTR + tid];
        s.Ht[tid] = acc * (1.f / 32.f);
    }
    __syncthreads();
    if (tid < 2) {
        float acc = fcb[tid];
#pragma unroll
        for (int k2 = 0; k2 < 64; k2++) acc += s.Ht[k2] * fcW[k2 * 2 + tid];
        s.ED[tid] = acc;
    }
    __syncthreads();
    if (tid == 0) {
        float l0 = s.ED[0], l1 = s.ED[1];
        out[g * 2 + 0] = l0;
        out[g * 2 + 1] = l1;
        float mx = fmaxf(l0, l1);
        float e0 = __expf(l0 - mx), e1 = __expf(l1 - mx);
        float inv = 1.f / (e0 + e1);
        out[out_half + g * 2 + 0] = e0 * inv;
        out[out_half + g * 2 + 1] = e1 * inv;
    }
}

extern "C" void kernel_launch(void* const* d_in, const int* in_sizes, int n_in,
                              void* d_out, int out_size)
{
    const float* x   = (const float*)d_in[0];
    const int*   ei  = (const int*)d_in[1];
    const float* Wq  = (const float*)d_in[3];
    const float* Wk  = (const float*)d_in[4];
    const float* Wv  = (const float*)d_in[5];
    const float* W1  = (const float*)d_in[6];
    const float* a1s = (const float*)d_in[7];
    const float* a1d = (const float*)d_in[8];
    const float* b1  = (const float*)d_in[9];
    const float* W2  = (const float*)d_in[10];
    const float* a2s = (const float*)d_in[11];
    const float* a2d = (const float*)d_in[12];
    const float* b2  = (const float*)d_in[13];
    const float* W3  = (const float*)d_in[14];
    const float* a3s = (const float*)d_in[15];
    const float* a3d = (const float*)d_in[16];
    const float* b3  = (const float*)d_in[17];
    const float* W4  = (const float*)d_in[18];
    const float* a4s = (const float*)d_in[19];
    const float* a4d = (const float*)d_in[20];
    const float* b4  = (const float*)d_in[21];
    const float* fcW = (const float*)d_in[22];
    const float* fcb = (const float*)d_in[23];

    gnn_kernel<<<NGRAPH, 128>>>(x, ei, Wq, Wk, Wv,
                                W1, a1s, a1d, b1,
                                W2, a2s, a2d, b2,
                                W3, a3s, a3d, b3,
                                W4, a4s, a4d, b4,
                                fcW, fcb,
                                (float*)d_out, out_size / 2);
}